// round 10
// baseline (speedup 1.0000x reference)
#include <cuda_runtime.h>

// LayerwiseLowRankUplift: out = z + U_l (V_l^T z), grouped by layer.
// Single fused persistent kernel: local grouping + split-K pass1 + per-layer
// reduction + spin-synchronized pass2. tf32 mma.sync.
// B=2048, H=2048, R=64, NL=32.

constexpr int B  = 2048;
constexpr int H  = 2048;
constexpr int R  = 64;
constexpr int NL = 32;

constexpr int KPART  = 8;           // split-K for pass 1 (8 blocks per layer)
constexpr int KSLICE = H / KPART;   // 256
constexpr int KCHUNK = 64;          // k per smem stage in pass 1
constexpr int HTILE2 = 128;         // h per pass-2 tile (16 tiles/layer, 2 per block)

// ---------------- device scratch (zero-init; protocol self-resets) ----------------
__device__ int  d_order[B];
__device__ int2 d_startcnt[NL];
__device__ __align__(16) float d_projp[(size_t)KPART * B * R];  // 4 MB partials
__device__ __align__(16) float d_proj[(size_t)B * R];           // reduced proj
__device__ int d_done1[NL];
__device__ int d_done2[NL];
__device__ int d_ready[NL];

// ---------------- shared memory union (exactly 48 KB) ----------------
struct SM1 {                        // pass-1 phase
    float zs[64 * 64];              // [s][k], swizzle col ^ ((row&7)<<2)
    float vs[64 * 64];              // [k][r], swizzle col ^ ((row&3)<<3)
    int   lord[B];                  // local stable order for this block's layer
    int   hist[NL];
    int   wtmp[8];
    int   isred;
};
struct SM2 {                        // pass-2 phase
    float us[HTILE2 * 64];          // [h][r], swizzle col ^ ((row&7)<<2)
    float ps[64 * 64];              // [s][r], swizzle col ^ ((row&7)<<2)
};
union SMem { SM1 p1; SM2 p2; };
static_assert(sizeof(SM2) == 49152, "");
static_assert(sizeof(SMem) == 49152, "");

// ---------------- tf32 MMA helper ----------------
__device__ __forceinline__ void mma_tf32(float* d, float a0, float a1, float a2, float a3,
                                         float b0, float b1) {
    asm volatile(
        "mma.sync.aligned.m16n8k8.row.col.f32.tf32.tf32.f32 "
        "{%0,%1,%2,%3}, {%4,%5,%6,%7}, {%8,%9}, {%0,%1,%2,%3};\n"
        : "+f"(d[0]), "+f"(d[1]), "+f"(d[2]), "+f"(d[3])
        : "r"(__float_as_uint(a0)), "r"(__float_as_uint(a1)),
          "r"(__float_as_uint(a2)), "r"(__float_as_uint(a3)),
          "r"(__float_as_uint(b0)), "r"(__float_as_uint(b1)));
}

// ---------------- the fused kernel: grid MUST be exactly KPART*NL = 256 blocks ----------------
__global__ __launch_bounds__(256, 2) void k_fused(const float* __restrict__ z,
                                                  const int*   __restrict__ lid,
                                                  const float* __restrict__ u,
                                                  const float* __restrict__ v,
                                                  float*       __restrict__ out) {
    __shared__ SMem sm;
    const int t = threadIdx.x, w = t >> 5, lane = t & 31;
    const int bid = blockIdx.x;
    const int l = bid & 31, kp = bid >> 5;

    // ================= stage A: local grouping for layer l =================
    int myl[8];
    #pragma unroll
    for (int j = 0; j < 8; j++) myl[j] = lid[j * 256 + t];
    if (t < NL) sm.p1.hist[t] = 0;
    __syncthreads();
    #pragma unroll
    for (int j = 0; j < 8; j++) atomicAdd(&sm.p1.hist[myl[j]], 1);
    __syncthreads();
    int start = 0;
    for (int i = 0; i < l; i++) start += sm.p1.hist[i];
    const int cnt = sm.p1.hist[l];
    __syncthreads();

    // stable compaction: ascending global index (j major, warp, lane)
    {
        int total = 0;
        #pragma unroll 1
        for (int j = 0; j < 8; j++) {
            bool p = (myl[j] == l);
            unsigned bal = __ballot_sync(0xffffffffu, p);
            if (lane == 0) sm.p1.wtmp[w] = __popc(bal);
            __syncthreads();
            int wbase = 0, rsum = 0;
            #pragma unroll
            for (int i = 0; i < 8; i++) {
                int c = sm.p1.wtmp[i];
                rsum += c;
                if (i < w) wbase += c;
            }
            if (p) {
                int pos = total + wbase + __popc(bal & ((1u << lane) - 1));
                sm.p1.lord[pos] = j * 256 + t;
                if (kp == 0) d_order[start + pos] = j * 256 + t;  // for pass-2 epilogue
            }
            total += rsum;
            __syncthreads();
        }
    }

    // ================= stage B: pass 1 for (kp, l) =================
    // Tile M=64 samples x N=64 r x K=KSLICE. 8 warps as 4m x 2n.
    if (cnt > 0) {
        const int m0 = (w & 3) * 16, n0 = (w >> 2) * 32;
        const int kbase = kp * KSLICE;
        const int row = t >> 2, q = t & 3;

        for (int s0 = 0; s0 < cnt; s0 += 64) {
            float acc[4][4] = {};

            for (int kc = 0; kc < KSLICE; kc += KCHUNK) {
                const int srow = s0 + row;
                const int b = (srow < cnt) ? sm.p1.lord[srow] : -1;
                #pragma unroll
                for (int j = 0; j < 4; j++) {
                    int col = q * 4 + j * 16;
                    float4 val = make_float4(0.f, 0.f, 0.f, 0.f);
                    if (b >= 0) val = *(const float4*)&z[(size_t)b * H + kbase + kc + col];
                    *(float4*)&sm.p1.zs[row * 64 + (col ^ ((row & 7) << 2))] = val;
                }
                #pragma unroll
                for (int j = 0; j < 4; j++) {
                    int col = q * 4 + j * 16;
                    float4 val = *(const float4*)&v[((size_t)l * H + kbase + kc + row) * R + col];
                    *(float4*)&sm.p1.vs[row * 64 + (col ^ ((row & 3) << 3))] = val;
                }
                __syncthreads();

                #pragma unroll
                for (int ks = 0; ks < 8; ks++) {
                    const int k0 = ks * 8;
                    const int ar = m0 + (lane >> 2);
                    const int ac = k0 + (lane & 3);
                    const int sw = (ar & 7) << 2;
                    float a0 = sm.p1.zs[ar * 64 + (ac ^ sw)];
                    float a1 = sm.p1.zs[(ar + 8) * 64 + (ac ^ sw)];
                    float a2 = sm.p1.zs[ar * 64 + ((ac + 4) ^ sw)];
                    float a3 = sm.p1.zs[(ar + 8) * 64 + ((ac + 4) ^ sw)];
                    const int br = k0 + (lane & 3);
                    const int bsw = (br & 3) << 3;
                    #pragma unroll
                    for (int nt = 0; nt < 4; nt++) {
                        int bc = n0 + nt * 8 + (lane >> 2);
                        float b0 = sm.p1.vs[br * 64 + (bc ^ bsw)];
                        float b1 = sm.p1.vs[(br + 4) * 64 + (bc ^ bsw)];
                        mma_tf32(acc[nt], a0, a1, a2, a3, b0, b1);
                    }
                }
                __syncthreads();
            }

            #pragma unroll
            for (int nt = 0; nt < 4; nt++) {
                int col = n0 + nt * 8 + 2 * (lane & 3);
                int sA = s0 + m0 + (lane >> 2);
                if (sA < cnt)
                    *(float2*)&d_projp[((size_t)kp * B + (start + sA)) * R + col] =
                        make_float2(acc[nt][0], acc[nt][1]);
                if (sA + 8 < cnt)
                    *(float2*)&d_projp[((size_t)kp * B + (start + sA + 8)) * R + col] =
                        make_float2(acc[nt][2], acc[nt][3]);
            }
            __syncthreads();
        }
    }

    // ================= stage B': release + last-arriver reduces partials =================
    if (t == 0) {
        __threadfence();                                   // release projp writes
        int old = atomicAdd(&d_done1[l], 1);
        sm.p1.isred = (old == KPART - 1);
    }
    __syncthreads();
    if (sm.p1.isred) {
        __threadfence();                                   // acquire all 8 blocks' projp
        const int n = cnt * R;
        for (int i = t; i < n; i += 256) {
            size_t base = (size_t)(start + (i >> 6)) * R + (i & 63);
            float acc = 0.f;
            #pragma unroll
            for (int kpp = 0; kpp < KPART; kpp++)
                acc += d_projp[(size_t)kpp * B * R + base];
            d_proj[base] = acc;
        }
        if (t == 0) d_startcnt[l] = make_int2(start, cnt);
        __syncthreads();
        if (t == 0) {
            __threadfence();                               // release d_proj/d_startcnt/d_order
            atomicExch(&d_ready[l], 1);
            atomicExch(&d_done1[l], 0);                    // reset for next graph replay
        }
    }
    __syncthreads();

    // ================= stage C: pass 2, two h-tiles of layer l =================
    {
        volatile int* rp = (volatile int*)&d_ready[l];
        while (*rp == 0) __nanosleep(64);
    }
    __threadfence();                                       // acquire (CCTL.IVALL -> fresh L1)
    const int2 sc = d_startcnt[l];
    const int start2 = sc.x, cnt2 = sc.y;
    __syncthreads();

    const int m0b = (w & 1) * 32, n0b = (w >> 1) * 32;
    const int q = t & 3;

    #pragma unroll 1
    for (int tilei = 0; tilei < 2; tilei++) {
        const int h0 = ((bid >> 5) + tilei * 8) * HTILE2;
        if (cnt2 > 0) {
            // load u tile (reused across sample stiles)
            #pragma unroll
            for (int i = 0; i < 2; i++) {
                int hrow = (t >> 2) + i * 64;
                #pragma unroll
                for (int j = 0; j < 4; j++) {
                    int col = q * 4 + j * 16;
                    float4 val = *(const float4*)&u[((size_t)l * H + h0 + hrow) * R + col];
                    *(float4*)&sm.p2.us[hrow * 64 + (col ^ ((hrow & 7) << 2))] = val;
                }
            }

            for (int s0 = 0; s0 < cnt2; s0 += 64) {
                // ps tile from reduced proj
                {
                    const int srow = t >> 2;
                    const bool valid = (s0 + srow) < cnt2;
                    #pragma unroll
                    for (int j = 0; j < 4; j++) {
                        int col = q * 4 + j * 16;
                        float4 a4 = make_float4(0.f, 0.f, 0.f, 0.f);
                        if (valid)
                            a4 = *(const float4*)&d_proj[(size_t)(start2 + s0 + srow) * R + col];
                        *(float4*)&sm.p2.ps[srow * 64 + (col ^ ((srow & 7) << 2))] = a4;
                    }
                }
                __syncthreads();

                float acc[2][4][4] = {};
                #pragma unroll
                for (int ks = 0; ks < 8; ks++) {
                    const int k0 = ks * 8;
                    float a[2][4];
                    #pragma unroll
                    for (int mi = 0; mi < 2; mi++) {
                        int ar = m0b + mi * 16 + (lane >> 2);
                        int ac = k0 + (lane & 3);
                        int sw = (ar & 7) << 2;
                        a[mi][0] = sm.p2.ps[ar * 64 + (ac ^ sw)];
                        a[mi][1] = sm.p2.ps[(ar + 8) * 64 + (ac ^ sw)];
                        a[mi][2] = sm.p2.ps[ar * 64 + ((ac + 4) ^ sw)];
                        a[mi][3] = sm.p2.ps[(ar + 8) * 64 + ((ac + 4) ^ sw)];
                    }
                    #pragma unroll
                    for (int nt = 0; nt < 4; nt++) {
                        int hr = n0b + nt * 8 + (lane >> 2);
                        int bk = k0 + (lane & 3);
                        int sw = (hr & 7) << 2;
                        float b0 = sm.p2.us[hr * 64 + (bk ^ sw)];
                        float b1 = sm.p2.us[hr * 64 + ((bk + 4) ^ sw)];
                        #pragma unroll
                        for (int mi = 0; mi < 2; mi++)
                            mma_tf32(acc[mi][nt], a[mi][0], a[mi][1], a[mi][2], a[mi][3], b0, b1);
                    }
                }

                // epilogue: out = z + delta (z in full fp32)
                #pragma unroll
                for (int mi = 0; mi < 2; mi++) {
                    int sr = s0 + m0b + mi * 16 + (lane >> 2);
                    int bA = (sr < cnt2) ? d_order[start2 + sr] : -1;
                    int bB = (sr + 8 < cnt2) ? d_order[start2 + sr + 8] : -1;
                    #pragma unroll
                    for (int nt = 0; nt < 4; nt++) {
                        int hcol = h0 + n0b + nt * 8 + 2 * (lane & 3);
                        if (bA >= 0) {
                            size_t off = (size_t)bA * H + hcol;
                            float2 zv = *(const float2*)&z[off];
                            *(float2*)&out[off] = make_float2(zv.x + acc[mi][nt][0],
                                                              zv.y + acc[mi][nt][1]);
                        }
                        if (bB >= 0) {
                            size_t off = (size_t)bB * H + hcol;
                            float2 zv = *(const float2*)&z[off];
                            *(float2*)&out[off] = make_float2(zv.x + acc[mi][nt][2],
                                                              zv.y + acc[mi][nt][3]);
                        }
                    }
                }
                __syncthreads();
            }
        }
        __syncthreads();
    }

    // completion: 8th pass-2 block of this layer resets flags for next replay
    if (t == 0) {
        int o2 = atomicAdd(&d_done2[l], 1);
        if (o2 == KPART - 1) {
            atomicExch(&d_ready[l], 0);
            atomicExch(&d_done2[l], 0);
        }
    }
}

// ---------------- launcher ----------------
extern "C" void kernel_launch(void* const* d_in, const int* in_sizes, int n_in,
                              void* d_out, int out_size) {
    const float* z   = (const float*)d_in[0];
    const int*   lid = (const int*)d_in[1];
    const float* u   = (const float*)d_in[2];
    const float* v   = (const float*)d_in[3];
    float* out = (float*)d_out;

    k_fused<<<KPART * NL, 256>>>(z, lid, u, v, out);  // grid MUST be 256 (co-residency)
}

// round 17
// speedup vs baseline: 1.0006x; 1.0006x over previous
#include <cuda_runtime.h>
#include <cstdint>
#include <cstddef>

// LayerwiseLowRankUplift: out = z + U_l (V_l^T z), grouped by layer.
// Two kernels, each with in-block grouping. tf32 mma.sync.
// Pass 1: cp.async double-buffered split-K GEMM + last-arriver reduction.
// Pass 2: 64x64 tiles, hoisted epilogue z loads.
// B=2048, H=2048, R=64, NL=32.

constexpr int B  = 2048;
constexpr int H  = 2048;
constexpr int R  = 64;
constexpr int NL = 32;

constexpr int KPART  = 16;          // split-K for pass 1
constexpr int KSLICE = H / KPART;   // 128
constexpr int KCHUNK = 32;          // k per pipeline stage
constexpr int NSTAGE = KSLICE / KCHUNK;  // 4

// ---------------- device scratch (zero-init; counters self-reset) ----------------
__device__ __align__(16) float d_projp[(size_t)KPART * B * R];  // 8 MB partials
__device__ __align__(16) float d_proj[(size_t)B * R];           // reduced proj
__device__ int d_done1[NL];

// ---------------- helpers ----------------
__device__ __forceinline__ unsigned smem_u32(const void* p) {
    return (unsigned)__cvta_generic_to_shared(p);
}
__device__ __forceinline__ void cp_async16(unsigned dst, const void* src, int szbytes) {
    asm volatile("cp.async.cg.shared.global [%0], [%1], 16, %2;\n"
                 :: "r"(dst), "l"(src), "r"(szbytes));
}
__device__ __forceinline__ void cp_commit() { asm volatile("cp.async.commit_group;\n"); }
template <int N>
__device__ __forceinline__ void cp_wait() {
    asm volatile("cp.async.wait_group %0;\n" :: "n"(N));
}
__device__ __forceinline__ void mma_tf32(float* d, float a0, float a1, float a2, float a3,
                                         float b0, float b1) {
    asm volatile(
        "mma.sync.aligned.m16n8k8.row.col.f32.tf32.tf32.f32 "
        "{%0,%1,%2,%3}, {%4,%5,%6,%7}, {%8,%9}, {%0,%1,%2,%3};\n"
        : "+f"(d[0]), "+f"(d[1]), "+f"(d[2]), "+f"(d[3])
        : "r"(__float_as_uint(a0)), "r"(__float_as_uint(a1)),
          "r"(__float_as_uint(a2)), "r"(__float_as_uint(a3)),
          "r"(__float_as_uint(b0)), "r"(__float_as_uint(b1)));
}

// ---------------- in-block grouping (stable: ascending global index) ----------------
// Every block computes the identical ordering for its layer -> deterministic.
struct GroupSM { int lord[B]; int hist[NL]; int wtmp[8]; };

__device__ __forceinline__ void block_group(GroupSM& g, const int* __restrict__ lid,
                                            int l, int t, int w, int lane,
                                            int& start, int& cnt) {
    int myl[8];
    #pragma unroll
    for (int j = 0; j < 8; j++) myl[j] = lid[j * 256 + t];
    if (t < NL) g.hist[t] = 0;
    __syncthreads();
    #pragma unroll
    for (int j = 0; j < 8; j++) atomicAdd(&g.hist[myl[j]], 1);
    __syncthreads();
    start = 0;
    for (int i = 0; i < l; i++) start += g.hist[i];
    cnt = g.hist[l];
    __syncthreads();
    int total = 0;
    #pragma unroll 1
    for (int j = 0; j < 8; j++) {
        bool p = (myl[j] == l);
        unsigned bal = __ballot_sync(0xffffffffu, p);
        if (lane == 0) g.wtmp[w] = __popc(bal);
        __syncthreads();
        int wbase = 0, rsum = 0;
        #pragma unroll
        for (int i = 0; i < 8; i++) {
            int c = g.wtmp[i];
            rsum += c;
            if (i < w) wbase += c;
        }
        if (p) g.lord[total + wbase + __popc(bal & ((1u << lane) - 1))] = j * 256 + t;
        total += rsum;
        __syncthreads();
    }
}

// ---------------- pass 1: proj = V_l^T z (split-K, cp.async pipelined) ----------------
// grid = KPART*NL = 512 blocks. Tile M=64 x N=64 x K=KSLICE. 8 warps 4m x 2n.
__global__ __launch_bounds__(256, 2) void k_pass1(const float* __restrict__ z,
                                                  const int*   __restrict__ lid,
                                                  const float* __restrict__ v) {
    __shared__ float zs[2][64 * 32];   // [s][k] swizzle col ^ ((row&7)<<2)
    __shared__ float vs[2][32 * 64];   // [k][r] swizzle col ^ ((row&3)<<3)
    __shared__ GroupSM g;

    const int t = threadIdx.x, w = t >> 5, lane = t & 31;
    const int l = blockIdx.x & 31, kp = blockIdx.x >> 5;
    int start, cnt;
    block_group(g, lid, l, t, w, lane, start, cnt);

    const int m0 = (w & 3) * 16, n0 = (w >> 2) * 32;
    const int kbase = kp * KSLICE;
    const int zrow = t >> 2, zq = t & 3;   // 64 rows x (4 thr x 2 float4)
    const int vrow = t >> 3, vq = t & 7;   // 32 rows x (8 thr x 2 float4)

    for (int s0 = 0; s0 < cnt; s0 += 64) {
        const int zb = (s0 + zrow < cnt) ? g.lord[s0 + zrow] : -1;
        const int zsz = (zb >= 0) ? 16 : 0;
        const float* zsrc0 = z + (size_t)max(zb, 0) * H + kbase;
        const float* vsrc0 = v + ((size_t)l * H + kbase + vrow) * R;

        // stage issue lambda
        auto issue = [&](int st, int buf) {
            #pragma unroll
            for (int j = 0; j < 2; j++) {
                int col = 4 * zq + 16 * j;
                cp_async16(smem_u32(&zs[buf][zrow * 32 + (col ^ ((zrow & 7) << 2))]),
                           zsrc0 + st * KCHUNK + col, zsz);
            }
            #pragma unroll
            for (int j = 0; j < 2; j++) {
                int col = 4 * vq + 32 * j;
                cp_async16(smem_u32(&vs[buf][vrow * 64 + (col ^ ((vrow & 3) << 3))]),
                           vsrc0 + (size_t)st * KCHUNK * R + col, 16);
            }
        };

        float acc[4][4] = {};
        issue(0, 0);
        cp_commit();
        #pragma unroll
        for (int st = 0; st < NSTAGE; st++) {
            const int buf = st & 1;
            if (st + 1 < NSTAGE) { issue(st + 1, (st + 1) & 1); cp_commit(); cp_wait<1>(); }
            else                 { cp_wait<0>(); }
            __syncthreads();

            #pragma unroll
            for (int ks = 0; ks < 4; ks++) {
                const int k0 = ks * 8;
                const int ar = m0 + (lane >> 2);
                const int ac = k0 + (lane & 3);
                const int sw = (ar & 7) << 2;
                float a0 = zs[buf][ar * 32 + (ac ^ sw)];
                float a1 = zs[buf][(ar + 8) * 32 + (ac ^ sw)];
                float a2 = zs[buf][ar * 32 + ((ac + 4) ^ sw)];
                float a3 = zs[buf][(ar + 8) * 32 + ((ac + 4) ^ sw)];
                const int br = k0 + (lane & 3);
                const int bsw = (br & 3) << 3;
                #pragma unroll
                for (int nt = 0; nt < 4; nt++) {
                    int bc = n0 + nt * 8 + (lane >> 2);
                    float b0 = vs[buf][br * 64 + (bc ^ bsw)];
                    float b1 = vs[buf][(br + 4) * 64 + (bc ^ bsw)];
                    mma_tf32(acc[nt], a0, a1, a2, a3, b0, b1);
                }
            }
            __syncthreads();
        }

        // store partials
        #pragma unroll
        for (int nt = 0; nt < 4; nt++) {
            int col = n0 + nt * 8 + 2 * (lane & 3);
            int sA = s0 + m0 + (lane >> 2);
            if (sA < cnt)
                *(float2*)&d_projp[((size_t)kp * B + (start + sA)) * R + col] =
                    make_float2(acc[nt][0], acc[nt][1]);
            if (sA + 8 < cnt)
                *(float2*)&d_projp[((size_t)kp * B + (start + sA + 8)) * R + col] =
                    make_float2(acc[nt][2], acc[nt][3]);
        }
        __syncthreads();
    }

    // last arriver of this layer reduces the KPART partials (fixed order -> deterministic)
    __shared__ int isred;
    if (t == 0) {
        __threadfence();
        isred = (atomicAdd(&d_done1[l], 1) == KPART - 1);
    }
    __syncthreads();
    if (isred) {
        __threadfence();   // acquire all blocks' partials
        const int n = cnt * R;
        for (int i = t; i < n; i += 256) {
            size_t base = (size_t)(start + (i >> 6)) * R + (i & 63);
            float acc = 0.f;
            #pragma unroll
            for (int kpp = 0; kpp < KPART; kpp++)
                acc += d_projp[(size_t)kpp * B * R + base];
            d_proj[base] = acc;
        }
        if (t == 0) atomicExch(&d_done1[l], 0);   // reset for next replay
    }
}

// ---------------- pass 2: out = z + proj U_l^T ----------------
// grid = 32 htiles * NL = 1024 blocks. Tile M=64 x N=64 x K=64. 8 warps 2m x 4n.
__global__ __launch_bounds__(256, 2) void k_pass2(const float* __restrict__ z,
                                                  const int*   __restrict__ lid,
                                                  const float* __restrict__ u,
                                                  float*       __restrict__ out) {
    __shared__ float us[64 * 64];   // [h][r] swizzle col ^ ((row&7)<<2)
    __shared__ float ps[64 * 64];   // [s][r] same swizzle
    __shared__ GroupSM g;

    const int t = threadIdx.x, w = t >> 5, lane = t & 31;
    const int l = blockIdx.x & 31, ht = blockIdx.x >> 5;
    const int h0 = ht * 64;
    int start, cnt;
    block_group(g, lid, l, t, w, lane, start, cnt);
    if (cnt == 0) return;

    const int m0 = (w & 1) * 32, n0 = (w >> 1) * 16;
    const int row = t >> 2, q = t & 3;

    // u tile once per block
    #pragma unroll
    for (int j = 0; j < 4; j++) {
        int col = 4 * q + 16 * j;
        float4 val = *(const float4*)&u[((size_t)l * H + h0 + row) * R + col];
        *(float4*)&us[row * 64 + (col ^ ((row & 7) << 2))] = val;
    }

    for (int s0 = 0; s0 < cnt; s0 += 64) {
        // ps tile from reduced proj
        {
            const bool valid = (s0 + row) < cnt;
            #pragma unroll
            for (int j = 0; j < 4; j++) {
                int col = 4 * q + 16 * j;
                float4 a4 = make_float4(0.f, 0.f, 0.f, 0.f);
                if (valid)
                    a4 = *(const float4*)&d_proj[(size_t)(start + s0 + row) * R + col];
                *(float4*)&ps[row * 64 + (col ^ ((row & 7) << 2))] = a4;
            }
        }

        // hoist epilogue z loads (hide DRAM latency under the MMA chain)
        int bA[2], bB[2];
        float2 zp[2][2][2];
        #pragma unroll
        for (int mi = 0; mi < 2; mi++) {
            int sr = s0 + m0 + 16 * mi + (lane >> 2);
            bA[mi] = (sr < cnt) ? g.lord[sr] : -1;
            bB[mi] = (sr + 8 < cnt) ? g.lord[sr + 8] : -1;
            #pragma unroll
            for (int nt = 0; nt < 2; nt++) {
                int hcol = h0 + n0 + nt * 8 + 2 * (lane & 3);
                zp[mi][nt][0] = (bA[mi] >= 0) ? *(const float2*)&z[(size_t)bA[mi] * H + hcol]
                                              : make_float2(0.f, 0.f);
                zp[mi][nt][1] = (bB[mi] >= 0) ? *(const float2*)&z[(size_t)bB[mi] * H + hcol]
                                              : make_float2(0.f, 0.f);
            }
        }
        __syncthreads();

        float acc[2][2][4] = {};
        #pragma unroll
        for (int ks = 0; ks < 8; ks++) {
            const int k0 = ks * 8;
            float a[2][4];
            #pragma unroll
            for (int mi = 0; mi < 2; mi++) {
                int ar = m0 + 16 * mi + (lane >> 2);
                int ac = k0 + (lane & 3);
                int sw = (ar & 7) << 2;
                a[mi][0] = ps[ar * 64 + (ac ^ sw)];
                a[mi][1] = ps[(ar + 8) * 64 + (ac ^ sw)];
                a[mi][2] = ps[ar * 64 + ((ac + 4) ^ sw)];
                a[mi][3] = ps[(ar + 8) * 64 + ((ac + 4) ^ sw)];
            }
            #pragma unroll
            for (int nt = 0; nt < 2; nt++) {
                int hr = n0 + nt * 8 + (lane >> 2);
                int bk = k0 + (lane & 3);
                int sw = (hr & 7) << 2;
                float b0 = us[hr * 64 + (bk ^ sw)];
                float b1 = us[hr * 64 + ((bk + 4) ^ sw)];
                #pragma unroll
                for (int mi = 0; mi < 2; mi++)
                    mma_tf32(acc[mi][nt], a[mi][0], a[mi][1], a[mi][2], a[mi][3], b0, b1);
            }
        }

        // epilogue: out = z + delta
        #pragma unroll
        for (int mi = 0; mi < 2; mi++) {
            #pragma unroll
            for (int nt = 0; nt < 2; nt++) {
                int hcol = h0 + n0 + nt * 8 + 2 * (lane & 3);
                if (bA[mi] >= 0) {
                    size_t off = (size_t)bA[mi] * H + hcol;
                    *(float2*)&out[off] = make_float2(zp[mi][nt][0].x + acc[mi][nt][0],
                                                      zp[mi][nt][0].y + acc[mi][nt][1]);
                }
                if (bB[mi] >= 0) {
                    size_t off = (size_t)bB[mi] * H + hcol;
                    *(float2*)&out[off] = make_float2(zp[mi][nt][1].x + acc[mi][nt][2],
                                                      zp[mi][nt][1].y + acc[mi][nt][3]);
                }
            }
        }
        __syncthreads();   // before next ps overwrite
    }
}

// ---------------- launcher ----------------
extern "C" void kernel_launch(void* const* d_in, const int* in_sizes, int n_in,
                              void* d_out, int out_size) {
    const float* z   = (const float*)d_in[0];
    const int*   lid = (const int*)d_in[1];
    const float* u   = (const float*)d_in[2];
    const float* v   = (const float*)d_in[3];
    float* out = (float*)d_out;

    k_pass1<<<KPART * NL, 256>>>(z, lid, v);
    k_pass2<<<32 * NL, 256>>>(z, lid, u, out);
}